// round 1
// baseline (speedup 1.0000x reference)
#include <cuda_runtime.h>
#include <cuda_bf16.h>

// Problem constants (fixed shapes from reference)
#define Nb 8
#define Ld 4096
#define Sd 4096
#define Hh 8
#define Dd 64
#define Mm 64
#define CH 8            // split-K chunks over S
#define SC (Sd / CH)    // 512 s-rows per chunk
#define EPSV 1e-6f

// Scratch (allocation-free rule: __device__ globals)
__device__ float g_KV[Nb * Hh * Dd * Mm];   // [n][h][d][m]
__device__ float g_Ksum[Nb * Hh * Dd];      // [n][h][d]

__device__ __forceinline__ float phi(float x) {
    // elu(x) + 1
    return x > 0.f ? x + 1.f : __expf(x);
}

__global__ void la_zero_kernel() {
    int idx = blockIdx.x * blockDim.x + threadIdx.x;
    if (idx < Nb * Hh * Dd * Mm) g_KV[idx] = 0.f;
    if (idx < Nb * Hh * Dd)      g_Ksum[idx] = 0.f;
}

// Phase 1: KV[d][m] += sum_s phi(K[s][d])*mask * V[s][m];  Ksum[d] += sum_s phi(K)[s][d]
// grid: (CH, H, N), block: 256 (16x16 threads, 4x4 register tile over 64x64 output)
__global__ void la_kv_kernel(const float* __restrict__ kk,
                             const float* __restrict__ vv,
                             const float* __restrict__ mask) {
    const int c = blockIdx.x, h = blockIdx.y, n = blockIdx.z;
    const int tid = threadIdx.x;
    const int tx = tid & 15, ty = tid >> 4;

    __shared__ float Ks[32 * 65];
    __shared__ float Vs[32 * 65];
    __shared__ float red[256];

    float acc[4][4] = {};
    float ksum_acc = 0.f;

    const int s0 = c * SC;
    const float* kbase = kk + (((size_t)n * Sd) * Hh + h) * Dd;
    const float* vbase = vv + (((size_t)n * Sd) * Hh + h) * Mm;
    const float* mbase = mask + (size_t)n * Sd;

    for (int sb = 0; sb < SC; sb += 32) {
        #pragma unroll
        for (int p = 0; p < 8; p++) {
            int idx = tid + p * 256;        // 0..2047
            int row = idx >> 6;             // 0..31
            int d   = idx & 63;             // == tid&63 (fixed per thread)
            int s   = s0 + sb + row;
            float kvv = kbase[(size_t)s * (Hh * Dd) + d];
            float kp  = phi(kvv) * mbase[s];
            Ks[row * 65 + d] = kp;
            ksum_acc += kp;
            Vs[row * 65 + d] = vbase[(size_t)s * (Hh * Mm) + d];
        }
        __syncthreads();
        #pragma unroll
        for (int ss = 0; ss < 32; ss++) {
            float a[4], b[4];
            #pragma unroll
            for (int i = 0; i < 4; i++) a[i] = Ks[ss * 65 + ty * 4 + i];
            #pragma unroll
            for (int j = 0; j < 4; j++) b[j] = Vs[ss * 65 + tx * 4 + j];
            #pragma unroll
            for (int i = 0; i < 4; i++)
                #pragma unroll
                for (int j = 0; j < 4; j++)
                    acc[i][j] += a[i] * b[j];
        }
        __syncthreads();
    }

    float* kvout = g_KV + ((size_t)(n * Hh + h)) * (Dd * Mm);
    #pragma unroll
    for (int i = 0; i < 4; i++)
        #pragma unroll
        for (int j = 0; j < 4; j++)
            atomicAdd(&kvout[(ty * 4 + i) * Mm + tx * 4 + j], acc[i][j]);

    red[tid] = ksum_acc;
    __syncthreads();
    if (tid < 64) {
        float s = red[tid] + red[tid + 64] + red[tid + 128] + red[tid + 192];
        atomicAdd(&g_Ksum[(n * Hh + h) * Dd + tid], s);
    }
}

// Phase 2: out[l][m] = (phi(Q)[l][:] . KV[:][m]) / (phi(Q)[l][:] . Ksum + eps)
// grid: (L/64, H, N), block: 256 (16x16, 4x4 tiles over 64x64 output)
__global__ void la_out_kernel(const float* __restrict__ qq,
                              float* __restrict__ out) {
    const int t = blockIdx.x, h = blockIdx.y, n = blockIdx.z;
    const int tid = threadIdx.x;
    const int tx = tid & 15, ty = tid >> 4;

    __shared__ float Qs[64 * 65];    // transposed: [d][l], phi applied
    __shared__ float KVs[64 * 65];   // [d][m]
    __shared__ float Ksum[64];
    __shared__ float Zs[64];
    __shared__ float red[256];

    const float* qbase = qq + ((((size_t)n * Ld + (size_t)t * 64) * Hh) + h) * Dd;

    #pragma unroll
    for (int p = 0; p < 16; p++) {
        int idx = tid + p * 256;     // 0..4095
        int l = idx >> 6, d = idx & 63;
        float qv = qbase[(size_t)l * (Hh * Dd) + d];
        Qs[d * 65 + l] = phi(qv);
    }
    const float* kvb = g_KV + ((size_t)(n * Hh + h)) * (Dd * Mm);
    #pragma unroll
    for (int p = 0; p < 16; p++) {
        int idx = tid + p * 256;
        int d = idx >> 6, m = idx & 63;
        KVs[d * 65 + m] = kvb[idx];
    }
    if (tid < 64) Ksum[tid] = g_Ksum[(n * Hh + h) * Dd + tid];
    __syncthreads();

    // Z per row: 4 threads per row, 16 d's each
    {
        int l = tid >> 2, dq = (tid & 3) * 16;
        float s = 0.f;
        #pragma unroll
        for (int i = 0; i < 16; i++) s += Qs[(dq + i) * 65 + l] * Ksum[dq + i];
        red[tid] = s;
    }
    __syncthreads();
    if (tid < 64) {
        float s = red[tid * 4] + red[tid * 4 + 1] + red[tid * 4 + 2] + red[tid * 4 + 3];
        Zs[tid] = 1.f / (s + EPSV);
    }
    __syncthreads();

    float acc[4][4] = {};
    #pragma unroll
    for (int d = 0; d < 64; d++) {
        float a[4], b[4];
        #pragma unroll
        for (int i = 0; i < 4; i++) a[i] = Qs[d * 65 + ty * 4 + i];
        #pragma unroll
        for (int j = 0; j < 4; j++) b[j] = KVs[d * 65 + tx * 4 + j];
        #pragma unroll
        for (int i = 0; i < 4; i++)
            #pragma unroll
            for (int j = 0; j < 4; j++)
                acc[i][j] += a[i] * b[j];
    }

    float* ob = out + ((((size_t)n * Ld + (size_t)t * 64) * Hh) + h) * Mm;
    #pragma unroll
    for (int i = 0; i < 4; i++) {
        int l = ty * 4 + i;
        float z = Zs[l];
        #pragma unroll
        for (int j = 0; j < 4; j++)
            ob[(size_t)l * (Hh * Mm) + tx * 4 + j] = acc[i][j] * z;
    }
}

extern "C" void kernel_launch(void* const* d_in, const int* in_sizes, int n_in,
                              void* d_out, int out_size) {
    const float* q    = (const float*)d_in[0];
    const float* k    = (const float*)d_in[1];
    const float* v    = (const float*)d_in[2];
    const float* mask = (const float*)d_in[3];
    float* out = (float*)d_out;

    la_zero_kernel<<<(Nb * Hh * Dd * Mm + 255) / 256, 256>>>();
    la_kv_kernel<<<dim3(CH, Hh, Nb), 256>>>(k, v, mask);
    la_out_kernel<<<dim3(Ld / 64, Hh, Nb), 256>>>(q, out);
}

// round 2
// speedup vs baseline: 2.4180x; 2.4180x over previous
#include <cuda_runtime.h>
#include <cuda_bf16.h>
#include <cstdint>

// Fixed shapes
#define Nb 8
#define Ld 4096
#define Sd 4096
#define Hh 8
#define Dd 64
#define Mm 64
#define CH 8            // split-K chunks over S
#define SC (Sd / CH)    // 512 s-rows per chunk
#define EPSV 1e-6f

// Scratch (allocation-free rule: __device__ globals)
__device__ float g_KV[Nb * Hh * Dd * Mm];   // [n][h][d][m]
__device__ float g_Ksum[Nb * Hh * Dd];      // [n][h][d]

__device__ __forceinline__ float phi(float x) {
    return x > 0.f ? x + 1.f : __expf(x);   // elu(x)+1
}

__device__ __forceinline__ uint32_t to_tf32(float x) {
    uint32_t u;
    asm("cvt.rna.tf32.f32 %0, %1;" : "=r"(u) : "f"(x));
    return u;
}

__device__ __forceinline__ void mma_tf32(float* d,
                                         uint32_t a0, uint32_t a1, uint32_t a2, uint32_t a3,
                                         uint32_t b0, uint32_t b1) {
    asm volatile(
        "mma.sync.aligned.m16n8k8.row.col.f32.tf32.tf32.f32 "
        "{%0,%1,%2,%3}, {%4,%5,%6,%7}, {%8,%9}, {%0,%1,%2,%3};\n"
        : "+f"(d[0]), "+f"(d[1]), "+f"(d[2]), "+f"(d[3])
        : "r"(a0), "r"(a1), "r"(a2), "r"(a3), "r"(b0), "r"(b1));
}

__global__ void la_zero_kernel() {
    int idx = blockIdx.x * blockDim.x + threadIdx.x;
    if (idx < Nb * Hh * Dd * Mm) g_KV[idx] = 0.f;
    if (idx < Nb * Hh * Dd)      g_Ksum[idx] = 0.f;
}

// Phase 1: KV[d][m] += sum_s phi(K[s][d])*mask * V[s][m];  Ksum[d] += sum_s phi(K)[s][d]
// grid (CH, H, N), 256 threads (8 warps). Warp w owns d-tile (w>>1)*16, m-tile (w&1)*32.
__global__ __launch_bounds__(256) void la_kv_kernel(const float* __restrict__ kk,
                                                    const float* __restrict__ vv,
                                                    const float* __restrict__ mask) {
    const int c = blockIdx.x, h = blockIdx.y, n = blockIdx.z;
    const int tid = threadIdx.x;
    const int warp = tid >> 5, lane = tid & 31;
    const int r = lane >> 2, q4 = lane & 3;
    const int d0 = (warp >> 1) * 16, m0 = (warp & 1) * 32;
    const int lrow = tid >> 4, lcol = tid & 15;

    __shared__ float Ks[32][72];   // [s][d], tf32 bit patterns
    __shared__ float Vs[32][72];   // [s][m], tf32 bit patterns
    __shared__ float ksum_s[64];

    if (tid < 64) ksum_s[tid] = 0.f;
    __syncthreads();

    float acc[4][4] = {};
    float ks4[4] = {0.f, 0.f, 0.f, 0.f};

    const size_t s0 = (size_t)c * SC;
    const float* kbase = kk + (size_t)n * Sd * (Hh * Dd) + h * Dd;
    const float* vbase = vv + (size_t)n * Sd * (Hh * Mm) + h * Mm;
    const float* mbase = mask + (size_t)n * Sd;

    for (int sb = 0; sb < SC; sb += 32) {
        #pragma unroll
        for (int p = 0; p < 2; p++) {
            int row = p * 16 + lrow;
            size_t sg = s0 + sb + row;
            float4 k4 = *(const float4*)(kbase + sg * 512 + lcol * 4);
            float4 v4 = *(const float4*)(vbase + sg * 512 + lcol * 4);
            float msk = __ldg(mbase + sg);
            float pk0 = phi(k4.x) * msk, pk1 = phi(k4.y) * msk;
            float pk2 = phi(k4.z) * msk, pk3 = phi(k4.w) * msk;
            ks4[0] += pk0; ks4[1] += pk1; ks4[2] += pk2; ks4[3] += pk3;
            uint4 ku; ku.x = to_tf32(pk0); ku.y = to_tf32(pk1);
                      ku.z = to_tf32(pk2); ku.w = to_tf32(pk3);
            uint4 vu; vu.x = to_tf32(v4.x); vu.y = to_tf32(v4.y);
                      vu.z = to_tf32(v4.z); vu.w = to_tf32(v4.w);
            *(uint4*)&Ks[row][lcol * 4] = ku;
            *(uint4*)&Vs[row][lcol * 4] = vu;
        }
        __syncthreads();

        #pragma unroll
        for (int k8 = 0; k8 < 4; k8++) {
            int sA = k8 * 8 + q4;
            uint32_t a0 = __float_as_uint(Ks[sA][d0 + r]);
            uint32_t a1 = __float_as_uint(Ks[sA][d0 + r + 8]);
            uint32_t a2 = __float_as_uint(Ks[sA + 4][d0 + r]);
            uint32_t a3 = __float_as_uint(Ks[sA + 4][d0 + r + 8]);
            #pragma unroll
            for (int j = 0; j < 4; j++) {
                uint32_t b0 = __float_as_uint(Vs[sA][m0 + 8 * j + r]);
                uint32_t b1 = __float_as_uint(Vs[sA + 4][m0 + 8 * j + r]);
                mma_tf32(acc[j], a0, a1, a2, a3, b0, b1);
            }
        }
        __syncthreads();
    }

    // Ksum reduction (fp32, independent of tf32 rounding)
    #pragma unroll
    for (int q = 0; q < 4; q++) atomicAdd(&ksum_s[lcol * 4 + q], ks4[q]);
    __syncthreads();
    if (tid < 64) atomicAdd(&g_Ksum[(n * Hh + h) * Dd + tid], ksum_s[tid]);

    float* kvout = g_KV + (size_t)(n * Hh + h) * (Dd * Mm);
    #pragma unroll
    for (int j = 0; j < 4; j++) {
        int m = m0 + 8 * j + 2 * q4;
        atomicAdd(&kvout[(d0 + r) * Mm + m],       acc[j][0]);
        atomicAdd(&kvout[(d0 + r) * Mm + m + 1],   acc[j][1]);
        atomicAdd(&kvout[(d0 + r + 8) * Mm + m],   acc[j][2]);
        atomicAdd(&kvout[(d0 + r + 8) * Mm + m + 1], acc[j][3]);
    }
}

// Phase 2: out[l][m] = (phiQ[l][:] . KV[:][m]) * z[l], z = 1/(phiQ.Ksum + eps)
// grid (L/64, H, N), 256 threads. Warp w: l-tile (w>>1)*16, m-tile (w&1)*32.
__global__ __launch_bounds__(256) void la_out_kernel(const float* __restrict__ qq,
                                                     float* __restrict__ out) {
    const int t = blockIdx.x, h = blockIdx.y, n = blockIdx.z;
    const int tid = threadIdx.x;
    const int warp = tid >> 5, lane = tid & 31;
    const int r = lane >> 2, q4 = lane & 3;
    const int l0 = (warp >> 1) * 16, m0 = (warp & 1) * 32;
    const int lrow = tid >> 4, lcol = tid & 15;

    __shared__ float Qs[64][76];    // [l][d], tf32-rounded phiQ
    __shared__ float KVs[64][72];   // [d][m], tf32
    __shared__ float KsumS[64];
    __shared__ float Zs[64];
    __shared__ float red[256];

    const float* qbase = qq + (((size_t)n * Ld + (size_t)t * 64) * Hh + h) * Dd;
    #pragma unroll
    for (int p = 0; p < 4; p++) {
        int row = p * 16 + lrow;
        float4 qv = *(const float4*)(qbase + (size_t)row * 512 + lcol * 4);
        uint4 qu; qu.x = to_tf32(phi(qv.x)); qu.y = to_tf32(phi(qv.y));
                  qu.z = to_tf32(phi(qv.z)); qu.w = to_tf32(phi(qv.w));
        *(uint4*)&Qs[row][lcol * 4] = qu;
    }
    const float* kvb = g_KV + (size_t)(n * Hh + h) * 4096;
    #pragma unroll
    for (int p = 0; p < 4; p++) {
        int idx4 = tid + p * 256;            // 0..1023 float4s
        float4 x = *(const float4*)(kvb + idx4 * 4);
        uint4 xu; xu.x = to_tf32(x.x); xu.y = to_tf32(x.y);
                  xu.z = to_tf32(x.z); xu.w = to_tf32(x.w);
        *(uint4*)&KVs[idx4 >> 4][(idx4 & 15) * 4] = xu;
    }
    if (tid < 64) KsumS[tid] = g_Ksum[(n * Hh + h) * Dd + tid];
    __syncthreads();

    // Z per row (fp32)
    {
        int l = tid >> 2, dq = (tid & 3) * 16;
        float s = 0.f;
        #pragma unroll
        for (int i = 0; i < 16; i++) s += Qs[l][dq + i] * KsumS[dq + i];
        red[tid] = s;
    }
    __syncthreads();
    if (tid < 64)
        Zs[tid] = 1.f / (red[tid * 4] + red[tid * 4 + 1] + red[tid * 4 + 2] + red[tid * 4 + 3] + EPSV);
    __syncthreads();

    float acc[4][4] = {};
    #pragma unroll
    for (int k8 = 0; k8 < 8; k8++) {
        int dk = k8 * 8;
        uint32_t a0 = __float_as_uint(Qs[l0 + r][dk + q4]);
        uint32_t a1 = __float_as_uint(Qs[l0 + r + 8][dk + q4]);
        uint32_t a2 = __float_as_uint(Qs[l0 + r][dk + q4 + 4]);
        uint32_t a3 = __float_as_uint(Qs[l0 + r + 8][dk + q4 + 4]);
        #pragma unroll
        for (int j = 0; j < 4; j++) {
            uint32_t b0 = __float_as_uint(KVs[dk + q4][m0 + 8 * j + r]);
            uint32_t b1 = __float_as_uint(KVs[dk + q4 + 4][m0 + 8 * j + r]);
            mma_tf32(acc[j], a0, a1, a2, a3, b0, b1);
        }
    }

    float* ob = out + (((size_t)n * Ld + (size_t)t * 64) * Hh + h) * Mm;
    #pragma unroll
    for (int j = 0; j < 4; j++) {
        int m = m0 + 8 * j + 2 * q4;
        int l1 = l0 + r, l2 = l0 + r + 8;
        float z1 = Zs[l1], z2 = Zs[l2];
        *(float2*)&ob[(size_t)l1 * 512 + m] = make_float2(acc[j][0] * z1, acc[j][1] * z1);
        *(float2*)&ob[(size_t)l2 * 512 + m] = make_float2(acc[j][2] * z2, acc[j][3] * z2);
    }
}

extern "C" void kernel_launch(void* const* d_in, const int* in_sizes, int n_in,
                              void* d_out, int out_size) {
    const float* q    = (const float*)d_in[0];
    const float* k    = (const float*)d_in[1];
    const float* v    = (const float*)d_in[2];
    const float* mask = (const float*)d_in[3];
    float* out = (float*)d_out;

    la_zero_kernel<<<(Nb * Hh * Dd * Mm + 255) / 256, 256>>>();
    la_kv_kernel<<<dim3(CH, Hh, Nb), 256>>>(k, v, mask);
    la_out_kernel<<<dim3(Ld / 64, Hh, Nb), 256>>>(q, out);
}

// round 3
// speedup vs baseline: 2.6139x; 1.0810x over previous
#include <cuda_runtime.h>
#include <cuda_bf16.h>
#include <cstdint>

// Fixed shapes
#define Nb 8
#define Ld 4096
#define Sd 4096
#define Hh 8
#define Dd 64
#define Mm 64
#define CH 8            // split-K chunks over S
#define SC (Sd / CH)    // 512 s-rows per chunk
#define EPSV 1e-6f
#define NH (Nb * Hh)

// Scratch (allocation-free rule: __device__ globals)
__device__ float g_KVp[CH * NH * Dd * Mm];   // per-chunk partial KV
__device__ float g_Ksp[CH * NH * Dd];        // per-chunk partial Ksum
__device__ float g_KV[NH * Dd * Mm];         // reduced KV
__device__ float g_Ksum[NH * Dd];            // reduced Ksum

__device__ __forceinline__ float phi(float x) {
    return x > 0.f ? x + 1.f : __expf(x);    // elu(x)+1
}

__device__ __forceinline__ uint32_t to_tf32(float x) {
    uint32_t u;
    asm("cvt.rna.tf32.f32 %0, %1;" : "=r"(u) : "f"(x));
    return u;
}

__device__ __forceinline__ void mma_tf32(float* d,
                                         uint32_t a0, uint32_t a1, uint32_t a2, uint32_t a3,
                                         uint32_t b0, uint32_t b1) {
    asm volatile(
        "mma.sync.aligned.m16n8k8.row.col.f32.tf32.tf32.f32 "
        "{%0,%1,%2,%3}, {%4,%5,%6,%7}, {%8,%9}, {%0,%1,%2,%3};\n"
        : "+f"(d[0]), "+f"(d[1]), "+f"(d[2]), "+f"(d[3])
        : "r"(a0), "r"(a1), "r"(a2), "r"(a3), "r"(b0), "r"(b1));
}

// ───────────────────────── Phase 1: per-chunk KV partials ─────────────────────────
// grid (CH, H, N), 256 threads (8 warps). Warp w: d-tile (w>>1)*16, m-tile (w&1)*32.
__global__ __launch_bounds__(256) void la_kv_kernel(const float* __restrict__ kk,
                                                    const float* __restrict__ vv,
                                                    const float* __restrict__ mask) {
    const int c = blockIdx.x, h = blockIdx.y, n = blockIdx.z;
    const int nh = n * Hh + h;
    const int tid = threadIdx.x;
    const int warp = tid >> 5, lane = tid & 31;
    const int r = lane >> 2, q4 = lane & 3;
    const int d0 = (warp >> 1) * 16, m0 = (warp & 1) * 32;
    const int lrow = tid >> 4, lcol = tid & 15;

    __shared__ float Ks[32][72];   // [s][d] tf32 bits
    __shared__ float Vs[32][72];   // [s][m] tf32 bits
    __shared__ float ksum_s[64];

    if (tid < 64) ksum_s[tid] = 0.f;

    float acc[4][4] = {};
    float ks4[4] = {0.f, 0.f, 0.f, 0.f};

    const size_t s0 = (size_t)c * SC;
    const float* kbase = kk + (size_t)n * Sd * 512 + h * Dd;
    const float* vbase = vv + (size_t)n * Sd * 512 + h * Mm;
    const float* mbase = mask + (size_t)n * Sd;

    // register prefetch buffers (2 rows per thread per tile)
    float4 kr[2], vr[2];
    float mr[2];

    // prefetch tile 0
    #pragma unroll
    for (int p = 0; p < 2; p++) {
        size_t sg = s0 + p * 16 + lrow;
        kr[p] = *(const float4*)(kbase + sg * 512 + lcol * 4);
        vr[p] = *(const float4*)(vbase + sg * 512 + lcol * 4);
        mr[p] = __ldg(mbase + sg);
    }

    for (int it = 0; it < SC / 32; it++) {
        // transform + store current tile to smem
        #pragma unroll
        for (int p = 0; p < 2; p++) {
            int row = p * 16 + lrow;
            float pk0 = phi(kr[p].x) * mr[p], pk1 = phi(kr[p].y) * mr[p];
            float pk2 = phi(kr[p].z) * mr[p], pk3 = phi(kr[p].w) * mr[p];
            ks4[0] += pk0; ks4[1] += pk1; ks4[2] += pk2; ks4[3] += pk3;
            uint4 ku; ku.x = to_tf32(pk0); ku.y = to_tf32(pk1);
                      ku.z = to_tf32(pk2); ku.w = to_tf32(pk3);
            uint4 vu; vu.x = to_tf32(vr[p].x); vu.y = to_tf32(vr[p].y);
                      vu.z = to_tf32(vr[p].z); vu.w = to_tf32(vr[p].w);
            *(uint4*)&Ks[row][lcol * 4] = ku;
            *(uint4*)&Vs[row][lcol * 4] = vu;
        }
        __syncthreads();

        // prefetch next tile (overlaps with mma below)
        if (it + 1 < SC / 32) {
            #pragma unroll
            for (int p = 0; p < 2; p++) {
                size_t sg = s0 + (it + 1) * 32 + p * 16 + lrow;
                kr[p] = *(const float4*)(kbase + sg * 512 + lcol * 4);
                vr[p] = *(const float4*)(vbase + sg * 512 + lcol * 4);
                mr[p] = __ldg(mbase + sg);
            }
        }

        #pragma unroll
        for (int k8 = 0; k8 < 4; k8++) {
            int sA = k8 * 8 + q4;
            uint32_t a0 = __float_as_uint(Ks[sA][d0 + r]);
            uint32_t a1 = __float_as_uint(Ks[sA][d0 + r + 8]);
            uint32_t a2 = __float_as_uint(Ks[sA + 4][d0 + r]);
            uint32_t a3 = __float_as_uint(Ks[sA + 4][d0 + r + 8]);
            #pragma unroll
            for (int j = 0; j < 4; j++) {
                uint32_t b0 = __float_as_uint(Vs[sA][m0 + 8 * j + r]);
                uint32_t b1 = __float_as_uint(Vs[sA + 4][m0 + 8 * j + r]);
                mma_tf32(acc[j], a0, a1, a2, a3, b0, b1);
            }
        }
        __syncthreads();
    }

    // Ksum partial (block reduce via shared atomics — once per kernel)
    #pragma unroll
    for (int q = 0; q < 4; q++) atomicAdd(&ksum_s[lcol * 4 + q], ks4[q]);
    __syncthreads();
    if (tid < 64) g_Ksp[(c * NH + nh) * Dd + tid] = ksum_s[tid];

    // KV partial: plain stores
    float* kvp = g_KVp + ((size_t)c * NH + nh) * (Dd * Mm);
    #pragma unroll
    for (int j = 0; j < 4; j++) {
        int m = m0 + 8 * j + 2 * q4;
        *(float2*)&kvp[(d0 + r) * Mm + m]     = make_float2(acc[j][0], acc[j][1]);
        *(float2*)&kvp[(d0 + r + 8) * Mm + m] = make_float2(acc[j][2], acc[j][3]);
    }
}

// ───────────────────────── Reduce: 8 partials → final KV/Ksum ─────────────────────
#define KV4 (NH * Dd * Mm / 4)     // 65536 float4
#define KS4 (NH * Dd / 4)          // 1024 float4
__global__ __launch_bounds__(256) void la_red_kernel() {
    int i = blockIdx.x * 256 + threadIdx.x;
    if (i < KV4) {
        float4 s = make_float4(0.f, 0.f, 0.f, 0.f);
        #pragma unroll
        for (int c = 0; c < CH; c++) {
            float4 x = *(const float4*)(g_KVp + (size_t)c * (NH * Dd * Mm) + i * 4);
            s.x += x.x; s.y += x.y; s.z += x.z; s.w += x.w;
        }
        *(float4*)(g_KV + i * 4) = s;
    } else if (i < KV4 + KS4) {
        int i2 = i - KV4;
        float4 s = make_float4(0.f, 0.f, 0.f, 0.f);
        #pragma unroll
        for (int c = 0; c < CH; c++) {
            float4 x = *(const float4*)(g_Ksp + c * (NH * Dd) + i2 * 4);
            s.x += x.x; s.y += x.y; s.z += x.z; s.w += x.w;
        }
        *(float4*)(g_Ksum + i2 * 4) = s;
    }
}

// ───────────────────────── Phase 2: out = (phiQ @ KV^T) * z ───────────────────────
// grid (L/64, H, N), 256 threads. Warp w: l-tile (w>>1)*16, m-tile (w&1)*32.
__global__ __launch_bounds__(256) void la_out_kernel(const float* __restrict__ qq,
                                                     float* __restrict__ out) {
    const int t = blockIdx.x, h = blockIdx.y, n = blockIdx.z;
    const int nh = n * Hh + h;
    const int tid = threadIdx.x;
    const int warp = tid >> 5, lane = tid & 31;
    const int r = lane >> 2, q4 = lane & 3;
    const int l0 = (warp >> 1) * 16, m0 = (warp & 1) * 32;
    const int lrow = tid >> 4, lcol = tid & 15;

    __shared__ float Qs[64][76];    // [l][d], tf32-rounded phiQ
    __shared__ float KVs[64][72];   // [d][m], tf32
    __shared__ float Zs[64];

    // Ksum slice for this thread's 4 d's (L2-hot: 64 CTAs share)
    float4 ksum4 = *(const float4*)(g_Ksum + nh * Dd + lcol * 4);

    const float* qbase = qq + (((size_t)n * Ld + (size_t)t * 64) * Hh + h) * Dd;
    #pragma unroll
    for (int p = 0; p < 4; p++) {
        int row = p * 16 + lrow;
        float4 qv = *(const float4*)(qbase + (size_t)row * 512 + lcol * 4);
        float p0 = phi(qv.x), p1 = phi(qv.y), p2 = phi(qv.z), p3 = phi(qv.w);
        // per-thread partial of phiQ . Ksum, reduced across the 16 lanes of this row
        float dot = p0 * ksum4.x + p1 * ksum4.y + p2 * ksum4.z + p3 * ksum4.w;
        dot += __shfl_xor_sync(0xffffffff, dot, 1);
        dot += __shfl_xor_sync(0xffffffff, dot, 2);
        dot += __shfl_xor_sync(0xffffffff, dot, 4);
        dot += __shfl_xor_sync(0xffffffff, dot, 8);
        if (lcol == 0) Zs[row] = 1.f / (dot + EPSV);
        uint4 qu; qu.x = to_tf32(p0); qu.y = to_tf32(p1);
                  qu.z = to_tf32(p2); qu.w = to_tf32(p3);
        *(uint4*)&Qs[row][lcol * 4] = qu;
    }

    const float* kvb = g_KV + (size_t)nh * (Dd * Mm);
    #pragma unroll
    for (int p = 0; p < 4; p++) {
        int idx4 = tid + p * 256;            // 0..1023 float4s
        float4 x = *(const float4*)(kvb + idx4 * 4);
        uint4 xu; xu.x = to_tf32(x.x); xu.y = to_tf32(x.y);
                  xu.z = to_tf32(x.z); xu.w = to_tf32(x.w);
        *(uint4*)&KVs[idx4 >> 4][(idx4 & 15) * 4] = xu;
    }
    __syncthreads();   // single barrier: smem tiles + Zs ready

    float acc[4][4] = {};
    #pragma unroll
    for (int k8 = 0; k8 < 8; k8++) {
        int dk = k8 * 8;
        uint32_t a0 = __float_as_uint(Qs[l0 + r][dk + q4]);
        uint32_t a1 = __float_as_uint(Qs[l0 + r + 8][dk + q4]);
        uint32_t a2 = __float_as_uint(Qs[l0 + r][dk + q4 + 4]);
        uint32_t a3 = __float_as_uint(Qs[l0 + r + 8][dk + q4 + 4]);
        #pragma unroll
        for (int j = 0; j < 4; j++) {
            uint32_t b0 = __float_as_uint(KVs[dk + q4][m0 + 8 * j + r]);
            uint32_t b1 = __float_as_uint(KVs[dk + q4 + 4][m0 + 8 * j + r]);
            mma_tf32(acc[j], a0, a1, a2, a3, b0, b1);
        }
    }

    float* ob = out + (((size_t)n * Ld + (size_t)t * 64) * Hh + h) * Mm;
    #pragma unroll
    for (int j = 0; j < 4; j++) {
        int m = m0 + 8 * j + 2 * q4;
        int l1 = l0 + r, l2 = l0 + r + 8;
        float z1 = Zs[l1], z2 = Zs[l2];
        *(float2*)&ob[(size_t)l1 * 512 + m] = make_float2(acc[j][0] * z1, acc[j][1] * z1);
        *(float2*)&ob[(size_t)l2 * 512 + m] = make_float2(acc[j][2] * z2, acc[j][3] * z2);
    }
}

extern "C" void kernel_launch(void* const* d_in, const int* in_sizes, int n_in,
                              void* d_out, int out_size) {
    const float* q    = (const float*)d_in[0];
    const float* k    = (const float*)d_in[1];
    const float* v    = (const float*)d_in[2];
    const float* mask = (const float*)d_in[3];
    float* out = (float*)d_out;

    la_kv_kernel<<<dim3(CH, Hh, Nb), 256>>>(k, v, mask);
    la_red_kernel<<<(KV4 + KS4 + 255) / 256, 256>>>();
    la_out_kernel<<<dim3(Ld / 64, Hh, Nb), 256>>>(q, out);
}